// round 9
// baseline (speedup 1.0000x reference)
#include <cuda_runtime.h>
#include <cuda_bf16.h>
#include <cstdint>

#define N_ANCH   2000000
#define N_GRP    (N_ANCH / 4)
#define K_SEL    2000
#define OUT_ROWS 1000
#define IMG_SZ   800.0f
#define MIN_SZ   16.0f
#define NMS_TH   0.7f

#define NFINE    4096
#define NCOARSE  65536
#define HI_CAP   262144
#define HI_LO    0.984375f          // 63/64
#define STAGE_CAP 1024

#define CTL_FLAG   0
#define CTL_NHI    1
#define CTL_NPAIRS 2
#define CTL_DONEA  3
#define CTL_DONEB  4

#define SCAN_NBLK  489              // ceil(500000 / 1024)

#define PAIR_GRID_X 8               // j chunks of 256
#define PAIR_GRID_Y 32              // i tiles of 64
#define PAIR_NBLK   (PAIR_GRID_X * PAIR_GRID_Y)

// -------- device scratch (zero-initialized at load; kernels self-clean) ----
__device__ unsigned int       g_hist_fine[NFINE];
__device__ unsigned int       g_hist_coarse[NCOARSE];
__device__ unsigned int       g_ctl[16];
__device__ unsigned long long g_hi[HI_CAP];
__device__ unsigned int       g_keys[N_ANCH];          // fallback only
__device__ float4             g_boxes[K_SEL];
__device__ unsigned char      g_validk[K_SEL];
__device__ unsigned int       g_pairs[2000000];

// -------- decode helper (matches reference math) --------
__device__ __forceinline__ float4 decode_box(float4 a, float4 l) {
    float w  = a.z - a.x;
    float h  = a.w - a.y;
    float cx = a.x + 0.5f * w;
    float cy = a.y + 0.5f * h;
    float pcx = cx + l.x * w;
    float pcy = cy + l.y * h;
    float pw  = w * expf(l.z);
    float ph  = h * expf(l.w);
    float x1 = fminf(fmaxf(pcx - 0.5f * pw, 0.0f), IMG_SZ);
    float y1 = fminf(fmaxf(pcy - 0.5f * ph, 0.0f), IMG_SZ);
    float x2 = fminf(fmaxf(pcx + 0.5f * pw, 0.0f), IMG_SZ);
    float y2 = fminf(fmaxf(pcy + 0.5f * ph, 0.0f), IMG_SZ);
    return make_float4(x1, y1, x2, y2);
}

// -------- fallback path (adversarial data only): exact full-range select ----
__device__ void fb_path(const float4* __restrict__ locs,
                        const float*  __restrict__ scores,
                        const float4* __restrict__ anchors,
                        unsigned int* A, unsigned int* B,
                        unsigned long long* sv, int* s_nc, unsigned int* s_T) {
    int t = threadIdx.x;
    for (int i = t; i < N_ANCH; i += 1024) {
        float4 d = decode_box(anchors[i], locs[i]);
        float  s = scores[i];
        bool valid = (d.z - d.x >= MIN_SZ) && (d.w - d.y >= MIN_SZ);
        unsigned int key = valid ? (__float_as_uint(s) + 1u) : 0u;
        g_keys[i] = key;
        if (key) {
            float sc = fmaxf(s, 0.0f);
            int b = (int)(sc * 65536.0f);
            if (b > NCOARSE - 1) b = NCOARSE - 1;
            float lo = (float)b * (1.0f / 65536.0f);
            if (sc < lo) b--;
            if (b < 0) b = 0;
            atomicAdd(&g_hist_coarse[b], 1u);
        }
    }
    __syncthreads();
    const unsigned int* h = &g_hist_coarse[t * 64];
    unsigned int s = 0;
    #pragma unroll 8
    for (int i = 0; i < 64; i++) s += h[i];
    A[t] = s;
    __syncthreads();
    unsigned int* src = A; unsigned int* dst = B;
    for (int d = 1; d < 1024; d <<= 1) {
        dst[t] = src[t] + (t + d < 1024 ? src[t + d] : 0u);
        __syncthreads();
        unsigned int* tmp = src; src = dst; dst = tmp;
    }
    unsigned int total = src[0];
    if (t == 0) *s_T = 1u;                       // default: every valid key
    __syncthreads();
    if (total >= (unsigned)K_SEL) {
        unsigned int suf  = src[t];
        unsigned int sufN = (t == 1023) ? 0u : src[t + 1];
        if (suf >= (unsigned)K_SEL && sufN < (unsigned)K_SEL) {
            unsigned int running = sufN;
            for (int i = 63; i >= 0; i--) {
                running += h[i];
                if (running >= (unsigned)K_SEL) {
                    *s_T = __float_as_uint((float)(t * 64 + i) * (1.0f / 65536.0f)) + 1u;
                    break;
                }
            }
        }
    }
    if (t == 0) *s_nc = 0;
    __syncthreads();
    unsigned int T = *s_T;
    for (int i = t; i < N_ANCH; i += 1024) {
        unsigned int key = g_keys[i];
        if (key >= T) {
            int p = atomicAdd(s_nc, 1);
            if (p < 4096)
                sv[p] = ((unsigned long long)key << 32) | (unsigned int)(~(unsigned)i);
        }
    }
    __syncthreads();
    int nc = *s_nc; if (nc > 4096) nc = 4096;
    int S = (nc <= 2048) ? 2048 : 4096;
    for (int i = nc + t; i < S; i += 1024) sv[i] = 0ULL;
    __syncthreads();
    int half = S >> 1;
    for (int k = 2; k <= S; k <<= 1) {
        for (int j = k >> 1; j > 0; j >>= 1) {
            for (int w = t; w < half; w += 1024) {
                int i = ((w & ~(j - 1)) << 1) | (w & (j - 1));
                int p = i | j;
                unsigned long long va = sv[i], vb = sv[p];
                bool up = ((i & k) == 0);
                if (up ? (va < vb) : (va > vb)) { sv[i] = vb; sv[p] = va; }
            }
            __syncthreads();
        }
    }
    for (int r = t; r < K_SEL; r += 1024) {
        unsigned long long v = sv[r];
        unsigned int key = (unsigned int)(v >> 32);
        unsigned int idx = ~(unsigned int)(v & 0xFFFFFFFFu);
        g_validk[r] = (key != 0u) ? 1 : 0;
        float4 box = make_float4(0.f, 0.f, 0.f, 0.f);
        if (key != 0u) box = decode_box(anchors[idx], locs[idx]);
        g_boxes[r] = box;
    }
    __syncthreads();
    for (int i = t; i < NCOARSE; i += 1024) g_hist_coarse[i] = 0u;  // self-clean
}

// -------- K1: score scan (1 float4/thread) + fused last-block top-k --------
__global__ void __launch_bounds__(1024) k_scan_top(const float4* __restrict__ locs,
                                                   const float*  __restrict__ scores,
                                                   const float4* __restrict__ scores4,
                                                   const float4* __restrict__ anchors) {
    __shared__ unsigned long long stage[STAGE_CAP];
    __shared__ int s_cnt;
    __shared__ unsigned int s_base;
    __shared__ int s_last;
    __shared__ unsigned int A[1024], B[1024];
    __shared__ unsigned long long sv[4096];
    __shared__ int s_nc;
    __shared__ unsigned int s_T;

    int t = threadIdx.x;
    if (t == 0) s_cnt = 0;
    __syncthreads();

    int g = blockIdx.x * 1024 + t;
    if (g < N_GRP) {
        float4 s4 = scores4[g];
        #pragma unroll
        for (int c = 0; c < 4; c++) {
            float s = (c == 0) ? s4.x : (c == 1) ? s4.y : (c == 2) ? s4.z : s4.w;
            if (s >= HI_LO) {
                int i = 4 * g + c;
                float4 d = decode_box(anchors[i], locs[i]);
                bool valid = (d.z - d.x >= MIN_SZ) && (d.w - d.y >= MIN_SZ);
                if (valid) {
                    int f = (int)(s * 262144.0f) - 258048;
                    if (f > NFINE - 1) f = NFINE - 1;
                    float lo = (float)(258048 + f) * (1.0f / 262144.0f);
                    if (s < lo) f--;
                    if (f >= 0) {
                        atomicAdd(&g_hist_fine[f], 1u);
                        unsigned int key = __float_as_uint(s) + 1u;
                        int p = atomicAdd(&s_cnt, 1);
                        if (p < STAGE_CAP)
                            stage[p] = ((unsigned long long)key << 32) | (unsigned int)(~(unsigned)i);
                        else
                            g_ctl[CTL_FLAG] = 1u;
                    }
                }
            }
        }
    }
    __syncthreads();
    int cnt = s_cnt;
    if (cnt > STAGE_CAP) cnt = STAGE_CAP;
    if (t == 0 && cnt > 0)
        s_base = atomicAdd(&g_ctl[CTL_NHI], (unsigned)cnt);
    __syncthreads();
    if (cnt > 0) {
        unsigned int b = s_base;
        for (int p = t; p < cnt; p += 1024)
            if (b + p < (unsigned)HI_CAP) g_hi[b + p] = stage[p];
            else g_ctl[CTL_FLAG] = 1u;
    }
    __syncthreads();

    // ---- ticket: last block proceeds to the top-k phase ----
    if (t == 0) {
        __threadfence();
        unsigned int old = atomicAdd(&g_ctl[CTL_DONEA], 1u);
        s_last = (old == (unsigned)(SCAN_NBLK - 1)) ? 1 : 0;
    }
    __syncthreads();
    if (!s_last) return;
    __threadfence();

    // ---- top-k phase (1024 threads) ----
    unsigned int* h = &g_hist_fine[t * 4];
    unsigned int h0 = h[0], h1 = h[1], h2 = h[2], h3 = h[3];
    h[0] = 0u; h[1] = 0u; h[2] = 0u; h[3] = 0u;        // self-clean
    A[t] = h0 + h1 + h2 + h3;
    __syncthreads();

    unsigned int* src = A; unsigned int* dst = B;
    for (int d = 1; d < 1024; d <<= 1) {
        dst[t] = src[t] + (t + d < 1024 ? src[t + d] : 0u);
        __syncthreads();
        unsigned int* tmp = src; src = dst; dst = tmp;
    }
    unsigned int total = src[0];
    unsigned int nhi   = g_ctl[CTL_NHI];
    bool fb = (g_ctl[CTL_FLAG] != 0u) || (total < (unsigned)K_SEL) || (nhi > (unsigned)HI_CAP);

    if (!fb) {
        unsigned int suf  = src[t];
        unsigned int sufN = (t == 1023) ? 0u : src[t + 1];
        if (suf >= (unsigned)K_SEL && sufN < (unsigned)K_SEL) {
            unsigned int running = sufN;
            unsigned int hv[4] = {h0, h1, h2, h3};
            for (int i = 3; i >= 0; i--) {
                running += hv[i];
                if (running >= (unsigned)K_SEL) {
                    s_T = __float_as_uint((float)(258048 + t * 4 + i) * (1.0f / 262144.0f)) + 1u;
                    break;
                }
            }
        }
        if (t == 0) s_nc = 0;
        __syncthreads();
        unsigned int T = s_T;
        for (int i = t; i < (int)nhi; i += 1024) {
            unsigned long long v = g_hi[i];
            if ((unsigned int)(v >> 32) >= T) {
                int p = atomicAdd(&s_nc, 1);
                if (p < 4096) sv[p] = v;
            }
        }
        __syncthreads();
        if (s_nc > 4096) fb = true;
    }

    if (fb) {
        if (t == 0) g_ctl[CTL_FLAG] = 1u;
        __syncthreads();
        fb_path(locs, scores, anchors, A, B, sv, &s_nc, &s_T);
        return;
    }

    int nc = s_nc;
    int S = (nc <= 2048) ? 2048 : 4096;
    for (int i = nc + t; i < S; i += 1024) sv[i] = 0ULL;
    __syncthreads();
    int half = S >> 1;
    for (int k = 2; k <= S; k <<= 1) {
        for (int j = k >> 1; j > 0; j >>= 1) {
            for (int w = t; w < half; w += 1024) {
                int i = ((w & ~(j - 1)) << 1) | (w & (j - 1));
                int p = i | j;
                unsigned long long va = sv[i], vb = sv[p];
                bool up = ((i & k) == 0);
                if (up ? (va < vb) : (va > vb)) { sv[i] = vb; sv[p] = va; }
            }
            __syncthreads();
        }
    }
    for (int r = t; r < K_SEL; r += 1024) {
        unsigned long long v = sv[r];
        unsigned int key = (unsigned int)(v >> 32);
        unsigned int idx = ~(unsigned int)(v & 0xFFFFFFFFu);
        g_validk[r] = (key != 0u) ? 1 : 0;
        float4 box = make_float4(0.f, 0.f, 0.f, 0.f);
        if (key != 0u) box = decode_box(anchors[idx], locs[idx]);
        g_boxes[r] = box;
    }
}

// -------- K2: pair extraction + (last block) Jacobi resolve + output --------
__global__ void __launch_bounds__(256) k_pairs(float* __restrict__ outf) {
    __shared__ float4 sb[64];
    __shared__ int s_last;
    __shared__ unsigned char ka[K_SEL], kb[K_SEL];
    __shared__ int changed;
    __shared__ int psA[2048], psB[2048];
    int t = threadIdx.x;
    int bi = blockIdx.y, bj = blockIdx.x;

    if (t < 64) {
        int ig = bi * 64 + t;
        sb[t] = (ig < K_SEL) ? g_boxes[ig] : make_float4(0.f, 0.f, 0.f, 0.f);
    }
    __syncthreads();

    bool active = (bi * 64 < bj * 256 + 256);
    int j = bj * 256 + t;
    if (active && j < K_SEL) {
        float4 bb = g_boxes[j];
        float aj = (bb.z - bb.x) * (bb.w - bb.y);
        for (int ii = 0; ii < 64; ii++) {
            int i = bi * 64 + ii;
            if (i >= j) break;
            float4 ba = sb[ii];
            float xx1 = fmaxf(ba.x, bb.x);
            float yy1 = fmaxf(ba.y, bb.y);
            float xx2 = fminf(ba.z, bb.z);
            float yy2 = fminf(ba.w, bb.w);
            float iw = fmaxf(xx2 - xx1, 0.0f);
            float ih = fmaxf(yy2 - yy1, 0.0f);
            float inter = iw * ih;
            float ai = (ba.z - ba.x) * (ba.w - ba.y);
            float u = fmaxf(ai + aj - inter, 1e-9f);
            if (inter > 0.699f * u) {                   // FMA prefilter
                if (inter / u > NMS_TH) {               // exact check, rare
                    unsigned int pos = atomicAdd(&g_ctl[CTL_NPAIRS], 1u);
                    g_pairs[pos] = ((unsigned)i << 11) | (unsigned)j;
                }
            }
        }
    }
    __syncthreads();
    if (t == 0) {
        __threadfence();
        unsigned int old = atomicAdd(&g_ctl[CTL_DONEB], 1u);
        s_last = (old == (unsigned)(PAIR_NBLK - 1)) ? 1 : 0;
    }
    __syncthreads();
    if (!s_last) return;
    __threadfence();

    // ---- last block: greedy-NMS Jacobi fixed point + compact + output ----
    int np = (int)g_ctl[CTL_NPAIRS];
    for (int jj = t; jj < K_SEL; jj += 256) ka[jj] = g_validk[jj];
    __syncthreads();
    for (int it = 0; it <= K_SEL; ++it) {
        if (t == 0) changed = 0;
        for (int jj = t; jj < K_SEL; jj += 256) kb[jj] = g_validk[jj];
        __syncthreads();
        for (int p = t; p < np; p += 256) {
            unsigned int pr = g_pairs[p];
            int i = (int)(pr >> 11), jj = (int)(pr & 2047u);
            if (ka[i]) kb[jj] = 0;
        }
        __syncthreads();
        for (int jj = t; jj < K_SEL; jj += 256) {
            if (kb[jj] != ka[jj]) { changed = 1; ka[jj] = kb[jj]; }
        }
        __syncthreads();
        int done = (changed == 0);
        __syncthreads();
        if (done) break;
    }
    for (int i = t; i < 2048; i += 256) psA[i] = (i < K_SEL) ? (int)ka[i] : 0;
    __syncthreads();
    int* src = psA; int* dst = psB;
    for (int d = 1; d < 2048; d <<= 1) {
        for (int i = t; i < 2048; i += 256)
            dst[i] = src[i] + (i >= d ? src[i - d] : 0);
        __syncthreads();
        int* t2 = src; src = dst; dst = t2;
    }
    float4* out4 = (float4*)outf;
    for (int r = t; r < OUT_ROWS; r += 256)
        out4[r] = make_float4(0.f, 0.f, 0.f, 0.f);
    __syncthreads();
    for (int jj = t; jj < K_SEL; jj += 256) {
        if (ka[jj]) {
            int pos = src[jj] - 1;
            if (pos < OUT_ROWS) out4[pos] = g_boxes[jj];
        }
    }
    __syncthreads();
    if (t < 16) g_ctl[t] = 0u;          // self-clean all control state
}

extern "C" void kernel_launch(void* const* d_in, const int* in_sizes, int n_in,
                              void* d_out, int out_size) {
    const float4* locs    = (const float4*)d_in[0];
    const float*  scores  = (const float*) d_in[1];
    const float4* scores4 = (const float4*)d_in[1];
    const float4* anchors = (const float4*)d_in[2];
    float* out = (float*)d_out;

    k_scan_top<<<SCAN_NBLK, 1024>>>(locs, scores, scores4, anchors);
    k_pairs<<<dim3(PAIR_GRID_X, PAIR_GRID_Y), 256>>>(out);
}

// round 10
// speedup vs baseline: 1.3426x; 1.3426x over previous
#include <cuda_runtime.h>
#include <cuda_bf16.h>
#include <cstdint>

#define N_ANCH   2000000
#define N_GRP    (N_ANCH / 4)
#define K_SEL    2000
#define OUT_ROWS 1000
#define IMG_SZ   800.0f
#define MIN_SZ   16.0f
#define NMS_TH   0.7f

#define NFINE    4096
#define NCOARSE  65536
#define HI_CAP   262144
#define HI_LO    0.984375f          // 63/64
#define STAGE_CAP 1024
#define PAIR_CAP  2000000           // >= 2000*1999/2, can never overflow

#define CTL_FLAG   0
#define CTL_NHI    1
#define CTL_NPAIRS 2

// -------- device scratch (zero-initialized at load; kernels self-clean) ----
__device__ unsigned int       g_hist_fine[NFINE];
__device__ unsigned int       g_hist_coarse[NCOARSE];
__device__ unsigned int       g_ctl[16];
__device__ unsigned long long g_hi[HI_CAP];
__device__ unsigned int       g_keys[N_ANCH];          // fallback only
__device__ float4             g_boxes[K_SEL];
__device__ unsigned char      g_validk[K_SEL];
__device__ unsigned int       g_pairs[PAIR_CAP];

// -------- decode helper (matches reference math) --------
__device__ __forceinline__ float4 decode_box(float4 a, float4 l) {
    float w  = a.z - a.x;
    float h  = a.w - a.y;
    float cx = a.x + 0.5f * w;
    float cy = a.y + 0.5f * h;
    float pcx = cx + l.x * w;
    float pcy = cy + l.y * h;
    float pw  = w * expf(l.z);
    float ph  = h * expf(l.w);
    float x1 = fminf(fmaxf(pcx - 0.5f * pw, 0.0f), IMG_SZ);
    float y1 = fminf(fmaxf(pcy - 0.5f * ph, 0.0f), IMG_SZ);
    float x2 = fminf(fmaxf(pcx + 0.5f * pw, 0.0f), IMG_SZ);
    float y2 = fminf(fmaxf(pcy + 0.5f * ph, 0.0f), IMG_SZ);
    return make_float4(x1, y1, x2, y2);
}

// -------- K1: score scan; sparse decode of hi-score elements --------
__global__ void __launch_bounds__(256) k_scan(const float4* __restrict__ locs,
                                              const float4* __restrict__ scores4,
                                              const float4* __restrict__ anchors) {
    __shared__ unsigned long long stage[STAGE_CAP];
    __shared__ int s_cnt;
    __shared__ unsigned int s_base;
    int t = threadIdx.x;
    if (t == 0) s_cnt = 0;
    __syncthreads();

    int g0 = blockIdx.x * 512 + t;
    int g1 = g0 + 256;
    float4 sA = (g0 < N_GRP) ? scores4[g0] : make_float4(0.f, 0.f, 0.f, 0.f);
    float4 sB = (g1 < N_GRP) ? scores4[g1] : make_float4(0.f, 0.f, 0.f, 0.f);
    #pragma unroll
    for (int half = 0; half < 2; half++) {
        int g = (half == 0) ? g0 : g1;
        float4 s4 = (half == 0) ? sA : sB;
        if (g >= N_GRP) continue;
        #pragma unroll
        for (int c = 0; c < 4; c++) {
            float s = (c == 0) ? s4.x : (c == 1) ? s4.y : (c == 2) ? s4.z : s4.w;
            if (s >= HI_LO) {
                int i = 4 * g + c;
                float4 d = decode_box(anchors[i], locs[i]);
                bool valid = (d.z - d.x >= MIN_SZ) && (d.w - d.y >= MIN_SZ);
                if (valid) {
                    int f = (int)(s * 262144.0f) - 258048;
                    if (f > NFINE - 1) f = NFINE - 1;
                    float lo = (float)(258048 + f) * (1.0f / 262144.0f);
                    if (s < lo) f--;
                    if (f >= 0) {
                        atomicAdd(&g_hist_fine[f], 1u);
                        unsigned int key = __float_as_uint(s) + 1u;
                        int p = atomicAdd(&s_cnt, 1);
                        if (p < STAGE_CAP)
                            stage[p] = ((unsigned long long)key << 32) | (unsigned int)(~(unsigned)i);
                        else
                            g_ctl[CTL_FLAG] = 1u;
                    }
                }
            }
        }
    }
    __syncthreads();
    int cnt = s_cnt;
    if (cnt > STAGE_CAP) cnt = STAGE_CAP;
    if (t == 0 && cnt > 0)
        s_base = atomicAdd(&g_ctl[CTL_NHI], (unsigned)cnt);
    __syncthreads();
    if (cnt > 0) {
        unsigned int b = s_base;
        for (int p = t; p < cnt; p += 256)
            if (b + p < (unsigned)HI_CAP) g_hi[b + p] = stage[p];
            else g_ctl[CTL_FLAG] = 1u;
    }
}

// -------- fallback path (adversarial data only): exact full-range select ----
__device__ void fb_path(const float4* __restrict__ locs,
                        const float*  __restrict__ scores,
                        const float4* __restrict__ anchors,
                        unsigned int* A, unsigned int* B,
                        unsigned long long* sv, int* s_nc, unsigned int* s_T) {
    int t = threadIdx.x;
    for (int i = t; i < N_ANCH; i += 1024) {
        float4 d = decode_box(anchors[i], locs[i]);
        float  s = scores[i];
        bool valid = (d.z - d.x >= MIN_SZ) && (d.w - d.y >= MIN_SZ);
        unsigned int key = valid ? (__float_as_uint(s) + 1u) : 0u;
        g_keys[i] = key;
        if (key) {
            float sc = fmaxf(s, 0.0f);
            int b = (int)(sc * 65536.0f);
            if (b > NCOARSE - 1) b = NCOARSE - 1;
            float lo = (float)b * (1.0f / 65536.0f);
            if (sc < lo) b--;
            if (b < 0) b = 0;
            atomicAdd(&g_hist_coarse[b], 1u);
        }
    }
    __syncthreads();
    const unsigned int* h = &g_hist_coarse[t * 64];
    unsigned int s = 0;
    #pragma unroll 8
    for (int i = 0; i < 64; i++) s += h[i];
    A[t] = s;
    __syncthreads();
    unsigned int* src = A; unsigned int* dst = B;
    for (int d = 1; d < 1024; d <<= 1) {
        dst[t] = src[t] + (t + d < 1024 ? src[t + d] : 0u);
        __syncthreads();
        unsigned int* tmp = src; src = dst; dst = tmp;
    }
    unsigned int total = src[0];
    if (t == 0) *s_T = 1u;                       // default: every valid key
    __syncthreads();
    if (total >= (unsigned)K_SEL) {
        unsigned int suf  = src[t];
        unsigned int sufN = (t == 1023) ? 0u : src[t + 1];
        if (suf >= (unsigned)K_SEL && sufN < (unsigned)K_SEL) {
            unsigned int running = sufN;
            for (int i = 63; i >= 0; i--) {
                running += h[i];
                if (running >= (unsigned)K_SEL) {
                    *s_T = __float_as_uint((float)(t * 64 + i) * (1.0f / 65536.0f)) + 1u;
                    break;
                }
            }
        }
    }
    if (t == 0) *s_nc = 0;
    __syncthreads();
    unsigned int T = *s_T;
    for (int i = t; i < N_ANCH; i += 1024) {
        unsigned int key = g_keys[i];
        if (key >= T) {
            int p = atomicAdd(s_nc, 1);
            if (p < 4096)
                sv[p] = ((unsigned long long)key << 32) | (unsigned int)(~(unsigned)i);
        }
    }
    __syncthreads();
    int nc = *s_nc; if (nc > 4096) nc = 4096;
    int S = (nc <= 2048) ? 2048 : 4096;
    for (int i = nc + t; i < S; i += 1024) sv[i] = 0ULL;
    __syncthreads();
    int half = S >> 1;
    for (int k = 2; k <= S; k <<= 1) {
        for (int j = k >> 1; j > 0; j >>= 1) {
            for (int w = t; w < half; w += 1024) {
                int i = ((w & ~(j - 1)) << 1) | (w & (j - 1));
                int p = i | j;
                unsigned long long va = sv[i], vb = sv[p];
                bool up = ((i & k) == 0);
                if (up ? (va < vb) : (va > vb)) { sv[i] = vb; sv[p] = va; }
            }
            __syncthreads();
        }
    }
    for (int r = t; r < K_SEL; r += 1024) {
        unsigned long long v = sv[r];
        unsigned int key = (unsigned int)(v >> 32);
        unsigned int idx = ~(unsigned int)(v & 0xFFFFFFFFu);
        g_validk[r] = (key != 0u) ? 1 : 0;
        float4 box = make_float4(0.f, 0.f, 0.f, 0.f);
        if (key != 0u) box = decode_box(anchors[idx], locs[idx]);
        g_boxes[r] = box;
    }
    __syncthreads();
    for (int i = t; i < NCOARSE; i += 1024) g_hist_coarse[i] = 0u;  // self-clean
}

// -------- K2: fused select + collect + sort + boxes (+ inline fallback) ----
__global__ void k_top(const float4* __restrict__ locs,
                      const float*  __restrict__ scores,
                      const float4* __restrict__ anchors) {
    __shared__ unsigned int A[1024], B[1024];
    __shared__ unsigned long long sv[4096];
    __shared__ int s_nc;
    __shared__ unsigned int s_T;
    int t = threadIdx.x;

    unsigned int* h = &g_hist_fine[t * 4];
    unsigned int h0 = h[0], h1 = h[1], h2 = h[2], h3 = h[3];
    h[0] = 0u; h[1] = 0u; h[2] = 0u; h[3] = 0u;        // self-clean for next replay
    A[t] = h0 + h1 + h2 + h3;
    __syncthreads();

    unsigned int* src = A; unsigned int* dst = B;
    for (int d = 1; d < 1024; d <<= 1) {
        dst[t] = src[t] + (t + d < 1024 ? src[t + d] : 0u);
        __syncthreads();
        unsigned int* tmp = src; src = dst; dst = tmp;
    }
    unsigned int total = src[0];
    unsigned int nhi   = g_ctl[CTL_NHI];
    bool fb = (g_ctl[CTL_FLAG] != 0u) || (total < (unsigned)K_SEL) || (nhi > (unsigned)HI_CAP);

    if (!fb) {
        unsigned int suf  = src[t];
        unsigned int sufN = (t == 1023) ? 0u : src[t + 1];
        if (suf >= (unsigned)K_SEL && sufN < (unsigned)K_SEL) {
            unsigned int running = sufN;
            unsigned int hv[4] = {h0, h1, h2, h3};
            for (int i = 3; i >= 0; i--) {
                running += hv[i];
                if (running >= (unsigned)K_SEL) {
                    s_T = __float_as_uint((float)(258048 + t * 4 + i) * (1.0f / 262144.0f)) + 1u;
                    break;
                }
            }
        }
        if (t == 0) s_nc = 0;
        __syncthreads();
        unsigned int T = s_T;
        for (int i = t; i < (int)nhi; i += 1024) {
            unsigned long long v = g_hi[i];
            if ((unsigned int)(v >> 32) >= T) {
                int p = atomicAdd(&s_nc, 1);
                if (p < 4096) sv[p] = v;
            }
        }
        __syncthreads();
        if (s_nc > 4096) fb = true;
    }

    if (fb) {
        if (t == 0) g_ctl[CTL_FLAG] = 1u;
        __syncthreads();
        fb_path(locs, scores, anchors, A, B, sv, &s_nc, &s_T);
        return;
    }

    int nc = s_nc;
    int S = (nc <= 2048) ? 2048 : 4096;
    for (int i = nc + t; i < S; i += 1024) sv[i] = 0ULL;
    __syncthreads();
    int half = S >> 1;
    for (int k = 2; k <= S; k <<= 1) {
        for (int j = k >> 1; j > 0; j >>= 1) {
            for (int w = t; w < half; w += 1024) {
                int i = ((w & ~(j - 1)) << 1) | (w & (j - 1));
                int p = i | j;
                unsigned long long va = sv[i], vb = sv[p];
                bool up = ((i & k) == 0);
                if (up ? (va < vb) : (va > vb)) { sv[i] = vb; sv[p] = va; }
            }
            __syncthreads();
        }
    }
    for (int r = t; r < K_SEL; r += 1024) {
        unsigned long long v = sv[r];
        unsigned int key = (unsigned int)(v >> 32);
        unsigned int idx = ~(unsigned int)(v & 0xFFFFFFFFu);
        g_validk[r] = (key != 0u) ? 1 : 0;
        float4 box = make_float4(0.f, 0.f, 0.f, 0.f);
        if (key != 0u) box = decode_box(anchors[idx], locs[idx]);
        g_boxes[r] = box;
    }
}

// -------- K3: flat candidate-pair extraction (NO division anywhere) --------
// One thread per (i,j): warp w covers j = by*8 + w/... (8 j's per block),
// lanes cover 32 consecutive i's. Conservative FMA prefilter 0.699;
// exact verification happens in k_resolve.
__global__ void __launch_bounds__(256) k_pairs() {
    int ic = blockIdx.x;                 // 32 i's
    int jc = blockIdx.y;                 // 8 j's
    if (ic * 32 >= jc * 8 + 8) return;   // uniform per block: tile entirely below diagonal
    int lane = threadIdx.x & 31;
    int w    = threadIdx.x >> 5;
    int i = ic * 32 + lane;
    int j = jc * 8 + w;
    bool hit = false;
    if (i < j && j < K_SEL) {
        float4 ba = g_boxes[i];
        float4 bb = g_boxes[j];
        float xx1 = fmaxf(ba.x, bb.x);
        float yy1 = fmaxf(ba.y, bb.y);
        float xx2 = fminf(ba.z, bb.z);
        float yy2 = fminf(ba.w, bb.w);
        float iw = fmaxf(xx2 - xx1, 0.0f);
        float ih = fmaxf(yy2 - yy1, 0.0f);
        float inter = iw * ih;
        float ai = (ba.z - ba.x) * (ba.w - ba.y);
        float aj = (bb.z - bb.x) * (bb.w - bb.y);
        float u = fmaxf(ai + aj - inter, 1e-9f);
        hit = (inter > 0.699f * u);      // conservative, division-free
    }
    unsigned int mask = __ballot_sync(0xFFFFFFFFu, hit);
    if (mask) {
        int leader = __ffs(mask) - 1;
        unsigned int basep = 0;
        if (lane == leader)
            basep = atomicAdd(&g_ctl[CTL_NPAIRS], (unsigned)__popc(mask));
        basep = __shfl_sync(0xFFFFFFFFu, basep, leader);
        if (hit) {
            int rank = __popc(mask & ((1u << lane) - 1u));
            unsigned int pos = basep + rank;
            if (pos < (unsigned)PAIR_CAP)
                g_pairs[pos] = ((unsigned)i << 11) | (unsigned)j;
        }
    }
}

// -------- K4: exact verify + Jacobi greedy-NMS + compact + output ----------
__global__ void k_resolve(float* __restrict__ outf) {
    __shared__ unsigned char ka[K_SEL], kb[K_SEL];
    __shared__ int changed;
    __shared__ int psA[2048], psB[2048];
    int t = threadIdx.x;
    int np = (int)g_ctl[CTL_NPAIRS];
    if (np > PAIR_CAP) np = PAIR_CAP;

    // exact re-verification of candidates (rare divisions live here only)
    for (int p = t; p < np; p += 1024) {
        unsigned int pr = g_pairs[p];
        int i = (int)(pr >> 11), j = (int)(pr & 2047u);
        float4 ba = g_boxes[i];
        float4 bb = g_boxes[j];
        float xx1 = fmaxf(ba.x, bb.x);
        float yy1 = fmaxf(ba.y, bb.y);
        float xx2 = fminf(ba.z, bb.z);
        float yy2 = fminf(ba.w, bb.w);
        float iw = fmaxf(xx2 - xx1, 0.0f);
        float ih = fmaxf(yy2 - yy1, 0.0f);
        float inter = iw * ih;
        float ai = (ba.z - ba.x) * (ba.w - ba.y);
        float aj = (bb.z - bb.x) * (bb.w - bb.y);
        float u = fmaxf(ai + aj - inter, 1e-9f);
        if (!(inter / u > NMS_TH)) g_pairs[p] = 0xFFFFFFFFu;   // exact reject
    }
    __syncthreads();

    for (int j = t; j < K_SEL; j += 1024) ka[j] = g_validk[j];
    __syncthreads();
    for (int it = 0; it <= K_SEL; ++it) {
        if (t == 0) changed = 0;
        for (int j = t; j < K_SEL; j += 1024) kb[j] = g_validk[j];
        __syncthreads();
        for (int p = t; p < np; p += 1024) {
            unsigned int pr = g_pairs[p];
            if (pr == 0xFFFFFFFFu) continue;
            int i = (int)(pr >> 11), j = (int)(pr & 2047u);
            if (ka[i]) kb[j] = 0;
        }
        __syncthreads();
        for (int j = t; j < K_SEL; j += 1024) {
            if (kb[j] != ka[j]) { changed = 1; ka[j] = kb[j]; }
        }
        __syncthreads();
        int done = (changed == 0);
        __syncthreads();
        if (done) break;
    }
    for (int i = t; i < 2048; i += 1024) psA[i] = (i < K_SEL) ? (int)ka[i] : 0;
    __syncthreads();
    int* src = psA; int* dst = psB;
    for (int d = 1; d < 2048; d <<= 1) {
        for (int i = t; i < 2048; i += 1024)
            dst[i] = src[i] + (i >= d ? src[i - d] : 0);
        __syncthreads();
        int* t2 = src; src = dst; dst = t2;
    }
    float4* out4 = (float4*)outf;
    for (int r = t; r < OUT_ROWS; r += 1024)
        out4[r] = make_float4(0.f, 0.f, 0.f, 0.f);
    __syncthreads();
    for (int j = t; j < K_SEL; j += 1024) {
        if (ka[j]) {
            int pos = src[j] - 1;
            if (pos < OUT_ROWS) out4[pos] = g_boxes[j];
        }
    }
    __syncthreads();
    if (t < 16) g_ctl[t] = 0u;          // self-clean all control state
}

extern "C" void kernel_launch(void* const* d_in, const int* in_sizes, int n_in,
                              void* d_out, int out_size) {
    const float4* locs    = (const float4*)d_in[0];
    const float*  scores  = (const float*) d_in[1];
    const float4* scores4 = (const float4*)d_in[1];
    const float4* anchors = (const float4*)d_in[2];
    float* out = (float*)d_out;

    k_scan<<<977, 256>>>(locs, scores4, anchors);
    k_top<<<1, 1024>>>(locs, scores, anchors);
    k_pairs<<<dim3(63, 250), 256>>>();
    k_resolve<<<1, 1024>>>(out);
}